// round 5
// baseline (speedup 1.0000x reference)
#include <cuda_runtime.h>
#include <math.h>
#include <stdint.h>

#define Bsz 256
#define Lsz 256
#define Dsz 128
#define Hh  2
#define Esz 64
#define NLay 2
#define TOPK 5

// ---------------- scratch (static device memory; no allocation) ----------------
__device__ float d_x   [Bsz*Lsz*Dsz];                 // activations fp32 (B,L,D)
__device__ __align__(16) uint32_t d_xp_hi[Bsz*Lsz*64], d_xp_lo[Bsz*Lsz*64];
__device__ float d_qkv [Bsz*Lsz*3*Dsz];               // q|k|v fp32, ld=384
__device__ __align__(16) uint32_t d_qkvp_hi[Bsz*128*384], d_qkvp_lo[Bsz*128*384];   // row-pairs
__device__ float d_fqkv[Bsz*Lsz*3*Dsz];               // fp32 (only v third valid)
__device__ __align__(16) uint32_t d_fqkvp_hi[Bsz*Lsz*192], d_fqkvp_lo[Bsz*Lsz*192]; // col-pairs
__device__ float d_S   [Bsz*Hh*Lsz*Lsz];              // raw scores fp32
__device__ __align__(16) uint32_t d_Sp_hi[Bsz*Hh*Lsz*128], d_Sp_lo[Bsz*Hh*Lsz*128];
__device__ float d_comb[Bsz*Lsz*Dsz];                 // freq (fp32), read by spatial
__device__ __align__(16) uint32_t d_combp_hi[Bsz*Lsz*64], d_combp_lo[Bsz*Lsz*64];
__device__ __align__(16) uint32_t d_ap_hi[Bsz*Lsz*64], d_ap_lo[Bsz*Lsz*64];
__device__ __align__(16) uint32_t d_hp_hi[Bsz*Lsz*128], d_hp_lo[Bsz*Lsz*128];
__device__ __align__(16) uint32_t d_Pp_hi[NLay*Lsz*128], d_Pp_lo[NLay*Lsz*128];
__device__ float d_Wcat[Dsz*3*Dsz];
__device__ __align__(16) uint32_t d_Wcatp_hi[64*384], d_Wcatp_lo[64*384];
__device__ __align__(16) uint32_t d_Wpp_hi[64*128],  d_Wpp_lo[64*128];
__device__ __align__(16) uint32_t d_F1p_hi[64*256],  d_F1p_lo[64*256];
__device__ __align__(16) uint32_t d_F2p_hi[128*128], d_F2p_lo[128*128];
__device__ float d_mv  [Bsz*Lsz];
__device__ int   d_delays[TOPK];
__device__ float d_tc  [Bsz*TOPK];
__device__ float d_maskv[Bsz*Lsz];

// ---------------- helpers ----------------
__device__ __forceinline__ float gelu_f(float v){
    return v * 0.5f * (1.0f + erff(v * 0.70710678118654752f));
}
__device__ __forceinline__ unsigned smem_u32(const void* p){
    return (unsigned)__cvta_generic_to_shared(p);
}
__device__ __forceinline__ void cp16(unsigned s, const void* g){
    asm volatile("cp.async.ca.shared.global [%0], [%1], 16;\n" :: "r"(s), "l"(g));
}
__device__ __forceinline__ float hipart(float x){
    return __uint_as_float(__float_as_uint(x) & 0xFFFF0000u);
}
__device__ __forceinline__ uint32_t packbf(float x, float y){
    return (__float_as_uint(x) >> 16) | (__float_as_uint(y) & 0xFFFF0000u);
}
__device__ __forceinline__ void splitpack(float x, float y, uint32_t& h, uint32_t& l){
    float hx = hipart(x), hy = hipart(y);
    h = packbf(x, y);
    l = packbf(x - hx, y - hy);
}
__device__ __forceinline__ void mma16(float* c, const uint32_t* a, const uint32_t* b){
    asm volatile(
      "mma.sync.aligned.m16n8k16.row.col.f32.bf16.bf16.f32 "
      "{%0,%1,%2,%3}, {%4,%5,%6,%7}, {%8,%9}, {%0,%1,%2,%3};\n"
      : "+f"(c[0]), "+f"(c[1]), "+f"(c[2]), "+f"(c[3])
      : "r"(a[0]), "r"(a[1]), "r"(a[2]), "r"(a[3]), "r"(b[0]), "r"(b[1]));
}

// ---------------- band-projection matrix P_k (emit packed bf16 pairs) ------------
__global__ void compute_P_kernel(){
    __shared__ float ct[256];
    __shared__ float rowv[256];
    int k = blockIdx.x >> 8;
    int n = blockIdx.x & 255;
    int m = threadIdx.x;
    ct[m] = cospif((float)m / 128.0f);
    __syncthreads();
    int lft = (k == 0) ? 51 : 0;
    int rgt = (k == 0) ? 129 : 78;
    int dnm = n - m;
    float s = 0.f;
    for (int f = lft; f < rgt; f++){
        float w = (f == 0 || f == 128) ? 1.f : 2.f;
        s += w * ct[(f * dnm) & 255];
    }
    rowv[m] = s * (1.0f/256.0f);
    __syncthreads();
    if (m < 128){
        uint32_t h, l;
        splitpack(rowv[2*m], rowv[2*m+1], h, l);
        d_Pp_hi[(k*256 + n)*128 + m] = h;
        d_Pp_lo[(k*256 + n)*128 + m] = l;
    }
}

// ---------------- embedding + mask (fp32 + packed) ----------------
__global__ void embed_kernel(const int* __restrict__ paths,
                             const float* __restrict__ ego,
                             const float* __restrict__ pos){
    __shared__ float sv[128];
    int bl = blockIdx.x;
    int d  = threadIdx.x;
    int p  = paths[bl];
    float v = ego[(long long)p*128 + d] + pos[(bl & 255)*128 + d];
    d_x[(long long)bl*128 + d] = v;
    sv[d] = v;
    if (d == 0) d_maskv[bl] = (p < 100000) ? 0.f : -10000.f;
    __syncthreads();
    if (d < 64){
        uint32_t h, l;
        splitpack(sv[2*d], sv[2*d+1], h, l);
        d_xp_hi[(long long)bl*64 + d] = h;
        d_xp_lo[(long long)bl*64 + d] = l;
    }
}

// ---------------- pack Wq|Wk|Wv into one 128x384 matrix ----------------
__global__ void packW_kernel(const float* __restrict__ wq,
                             const float* __restrict__ wk,
                             const float* __restrict__ wv){
    int i = blockIdx.x*256 + threadIdx.x;      // 49152 total
    int r = i / 384, c = i % 384;
    const float* src = (c < 128) ? wq : ((c < 256) ? wk : wv);
    d_Wcat[i] = src[r*128 + (c & 127)];
}

// ---------------- row-pair packing: src[K][N] fp32 -> hi/lo[K/2][N] --------------
__global__ void packrows_kernel(const float* __restrict__ src,
                                uint32_t* __restrict__ hi, uint32_t* __restrict__ lo,
                                int N, int total){
    int o = blockIdx.x*256 + threadIdx.x;
    if (o >= total) return;
    int p = o / N, n = o - p*N;
    float a = src[(long long)(2*p)*N + n];
    float b = src[(long long)(2*p+1)*N + n];
    uint32_t h, l;
    splitpack(a, b, h, l);
    hi[o] = h; lo[o] = l;
}

// ---------------- tensor-core GEMM on pre-split packed bf16 operands -------------
// EPI: 0 plain, 1 +=X residual, 2 gelu, 3 C-read accumulate (alpha*AB + C)
// BMODE: 0 = packed non-TB ([k/2][n]), 1 = packed TB ([n][k/2]), 2 = fp32 non-TB
template<int EPI, int BMODE, int BN>
__global__ void __launch_bounds__(256) gemm_tc(
    const uint32_t* __restrict__ Ahg, const uint32_t* __restrict__ Alg,
    const void* __restrict__ Bhg_v, const void* __restrict__ Blg_v,
    float* __restrict__ Cg, uint32_t* __restrict__ Cphg, uint32_t* __restrict__ Cplg,
    const float* __restrict__ Xg,
    int M, int N, int K, int lda, int ldb, int ldc, int ldcp,
    long long sAb, long long sAh, long long sBb, long long sBh,
    long long sCb, long long sCh, long long sCpb, long long sCph,
    int Hdim, float alpha, int n0f)
{
    constexpr int BM = 128, BK = 16;
    constexpr int APW = 12;                      // packed A smem row stride (u32)
    constexpr int ABYTES = 2*BM*APW*4;           // per hi/lo (both stages)
    constexpr int BBYTES = (BMODE==0) ? 2*8*136*4
                         : (BMODE==1) ? 2*BN*12*4 : 2*16*68*4;
    constexpr int TOTB = 2*ABYTES + ((BMODE==2) ? BBYTES : 2*BBYTES);
    __shared__ __align__(16) unsigned char smembuf[TOTB];
    uint32_t* Ash = (uint32_t*)smembuf;
    uint32_t* Asl = (uint32_t*)(smembuf + ABYTES);
    uint32_t* Bsh = (uint32_t*)(smembuf + 2*ABYTES);
    uint32_t* Bsl = (uint32_t*)(smembuf + 2*ABYTES + BBYTES);
    float*    Bsf = (float*)   (smembuf + 2*ABYTES);

    constexpr int WCOLS = (BN == 128) ? 4 : 2;
    constexpr int WM    = (BN == 128) ? 64 : 32;
    constexpr int MT = WM / 16;
    constexpr int NT = 4;

    int z  = blockIdx.z;
    int bb = z / Hdim, hh = z - bb*Hdim;
    const uint32_t* Ah_ = Ahg + bb*sAb + hh*sAh;
    const uint32_t* Al_ = Alg + bb*sAb + hh*sAh;
    const uint32_t* Bhp = (const uint32_t*)Bhg_v;
    const uint32_t* Blp = (const uint32_t*)Blg_v;
    const float*    Bfp = (const float*)Bhg_v;
    if (BMODE != 2){ Bhp += bb*sBb + hh*sBh; Blp += bb*sBb + hh*sBh; }
    else           { Bfp += bb*sBb + hh*sBh; }
    float* C = Cg ? (Cg + bb*sCb + hh*sCh) : nullptr;
    uint32_t* Cph = Cphg ? (Cphg + bb*sCpb + hh*sCph) : nullptr;
    uint32_t* Cpl = Cplg ? (Cplg + bb*sCpb + hh*sCph) : nullptr;

    int m0 = blockIdx.y * BM;
    int n0 = blockIdx.x * BN;
    int tid = threadIdx.x;
    int warp = tid >> 5, lane = tid & 31;
    int wm = warp / WCOLS, wn = warp % WCOLS;
    int wm0 = wm*WM, wn0 = wn*32;
    int g4 = lane >> 2, tg = lane & 3;

    float acc[MT][NT][4];
    #pragma unroll
    for (int i = 0; i < MT; i++)
        #pragma unroll
        for (int j = 0; j < NT; j++)
            #pragma unroll
            for (int r = 0; r < 4; r++) acc[i][j][r] = 0.f;

    const int KT = K / BK;

    // ---- stage loaders (all 16B cp.async) ----
    #define LOAD_A(st, k0u) {                                                     \
        int row = tid >> 1, seg = (tid & 1) * 4;                                  \
        const uint32_t* srcH = Ah_ + (long long)(m0+row)*lda + (k0u) + seg;       \
        const uint32_t* srcL = Al_ + (long long)(m0+row)*lda + (k0u) + seg;       \
        cp16(smem_u32(&Ash[(st)*BM*APW + row*APW + seg]), srcH);                  \
        cp16(smem_u32(&Asl[(st)*BM*APW + row*APW + seg]), srcL);                  \
    }
    #define LOAD_B(st, k0, k0u) {                                                 \
        if (BMODE == 0){                                                          \
            int kp = tid >> 5, nc = (tid & 31) * 4;                               \
            const uint32_t* sH = Bhp + (long long)((k0u)+kp)*ldb + n0 + nc;       \
            const uint32_t* sL = Blp + (long long)((k0u)+kp)*ldb + n0 + nc;       \
            cp16(smem_u32(&Bsh[(st)*8*136 + kp*136 + nc]), sH);                   \
            cp16(smem_u32(&Bsl[(st)*8*136 + kp*136 + nc]), sL);                   \
        } else if (BMODE == 1){                                                   \
            int row = tid >> 1, seg = (tid & 1) * 4;                              \
            const uint32_t* sH = Bhp + (long long)(n0+row)*ldb + (k0u) + seg;     \
            const uint32_t* sL = Blp + (long long)(n0+row)*ldb + (k0u) + seg;     \
            cp16(smem_u32(&Bsh[(st)*BN*12 + row*12 + seg]), sH);                  \
            cp16(smem_u32(&Bsl[(st)*BN*12 + row*12 + seg]), sL);                  \
        } else {                                                                  \
            int row = tid >> 4, nc = (tid & 15) * 4;                              \
            const float* sF = Bfp + (long long)((k0)+row)*ldb + n0 + nc;          \
            cp16(smem_u32(&Bsf[(st)*16*68 + row*68 + nc]), sF);                   \
        }                                                                         \
    }

    LOAD_A(0, 0); LOAD_B(0, 0, 0);
    asm volatile("cp.async.commit_group;\n");

    for (int kt = 0; kt < KT; kt++){
        int cur = kt & 1;
        if (kt + 1 < KT){
            int nxt = (kt + 1) & 1;
            LOAD_A(nxt, (kt+1)*(BK/2)); LOAD_B(nxt, (kt+1)*BK, (kt+1)*(BK/2));
            asm volatile("cp.async.commit_group;\n");
            asm volatile("cp.async.wait_group 1;\n");
        } else {
            asm volatile("cp.async.wait_group 0;\n");
        }
        __syncthreads();

        const uint32_t* ah = Ash + cur*BM*APW;
        const uint32_t* al = Asl + cur*BM*APW;
        uint32_t Ahf[MT][4], Alf[MT][4], Bhf[NT][2], Blf[NT][2];
        #pragma unroll
        for (int i = 0; i < MT; i++){
            int r = wm0 + i*16 + g4;
            Ahf[i][0] = ah[ r     *APW + tg    ];
            Ahf[i][1] = ah[(r + 8)*APW + tg    ];
            Ahf[i][2] = ah[ r     *APW + tg + 4];
            Ahf[i][3] = ah[(r + 8)*APW + tg + 4];
            Alf[i][0] = al[ r     *APW + tg    ];
            Alf[i][1] = al[(r + 8)*APW + tg    ];
            Alf[i][2] = al[ r     *APW + tg + 4];
            Alf[i][3] = al[(r + 8)*APW + tg + 4];
        }
        #pragma unroll
        for (int j = 0; j < NT; j++){
            int n = wn0 + j*8 + g4;
            if (BMODE == 0){
                const uint32_t* bh = Bsh + cur*8*136;
                const uint32_t* bl = Bsl + cur*8*136;
                Bhf[j][0] = bh[ tg     *136 + n];
                Bhf[j][1] = bh[(tg + 4)*136 + n];
                Blf[j][0] = bl[ tg     *136 + n];
                Blf[j][1] = bl[(tg + 4)*136 + n];
            } else if (BMODE == 1){
                const uint32_t* bh = Bsh + cur*BN*12;
                const uint32_t* bl = Bsl + cur*BN*12;
                Bhf[j][0] = bh[n*12 + tg    ];
                Bhf[j][1] = bh[n*12 + tg + 4];
                Blf[j][0] = bl[n*12 + tg    ];
                Blf[j][1] = bl[n*12 + tg + 4];
            } else {
                const float* bf = Bsf + cur*16*68;
                float b00 = bf[(2*tg    )*68 + n];
                float b01 = bf[(2*tg + 1)*68 + n];
                float b10 = bf[(2*tg + 8)*68 + n];
                float b11 = bf[(2*tg + 9)*68 + n];
                splitpack(b00, b01, Bhf[j][0], Blf[j][0]);
                splitpack(b10, b11, Bhf[j][1], Blf[j][1]);
            }
        }
        #pragma unroll
        for (int i = 0; i < MT; i++)
            #pragma unroll
            for (int j = 0; j < NT; j++){
                mma16(acc[i][j], Ahf[i], Bhf[j]);
                mma16(acc[i][j], Ahf[i], Blf[j]);
                mma16(acc[i][j], Alf[i], Bhf[j]);
            }
        __syncthreads();
    }

    // ---- epilogue ----
    bool wrf = (C != nullptr) && (n0 >= n0f);
    #pragma unroll
    for (int i = 0; i < MT; i++)
        #pragma unroll
        for (int j = 0; j < NT; j++){
            int row = m0 + wm0 + i*16 + g4;
            int col = n0 + wn0 + j*8 + tg*2;
            #pragma unroll
            for (int h = 0; h < 2; h++){
                long long off = (long long)(row + h*8)*ldc + col;
                float vx = acc[i][j][h*2+0]*alpha;
                float vy = acc[i][j][h*2+1]*alpha;
                if (EPI == 1){ float2 xv = *(const float2*)&Xg[off]; vx += xv.x; vy += xv.y; }
                if (EPI == 2){ vx = gelu_f(vx); vy = gelu_f(vy); }
                if (EPI == 3){ float2 cv = *(const float2*)&C[off]; vx += cv.x; vy += cv.y; }
                if (wrf){ float2 r; r.x = vx; r.y = vy; *(float2*)&C[off] = r; }
                if (Cph){
                    long long op = (long long)(row + h*8)*ldcp + (col >> 1);
                    uint32_t hb, lb;
                    splitpack(vx, vy, hb, lb);
                    Cph[op] = hb; Cpl[op] = lb;
                }
            }
        }
    #undef LOAD_A
    #undef LOAD_B
}

// ---------------- circular-diagonal sums of raw scores -> mean_value ----------------
__global__ void __launch_bounds__(256) diag_sum_kernel(){
    int b = blockIdx.x;
    __shared__ float acc[8][256];
    int tid = threadIdx.x;
    int warp = tid >> 5, lane = tid & 31;
    for (int i = tid; i < 8*256; i += 256) ((float*)acc)[i] = 0.f;
    __syncthreads();
    for (int h = 0; h < 2; h++){
        const float* S = d_S + ((long long)(b*2 + h)) * 65536;
        for (int i = warp; i < 256; i += 8){
            const float* row = S + i*256;
            #pragma unroll
            for (int c = 0; c < 8; c++){
                int t = c*32 + lane;
                acc[warp][(i - t) & 255] += row[t];
            }
        }
    }
    __syncthreads();
    float s = 0.f;
    #pragma unroll
    for (int w = 0; w < 8; w++) s += acc[w][tid];
    d_mv[b*256 + tid] = s * (1.0f/128.0f);
}

// ---------------- global top-5 over mean over B ----------------
__global__ void topk_kernel(){
    int n = threadIdx.x;
    float s = 0.f;
    for (int b = 0; b < 256; b++) s += d_mv[b*256 + n];
    __shared__ float sg[256];
    sg[n] = s;
    __syncthreads();
    if (n == 0){
        for (int t = 0; t < TOPK; t++){
            int bi = 0; float bv = sg[0];
            for (int i = 1; i < 256; i++) if (sg[i] > bv){ bv = sg[i]; bi = i; }
            d_delays[t] = bi;
            sg[bi] = -1e30f;
        }
    }
}

// ---------------- per-batch softmax over the 5 selected weights ----------------
__global__ void weights_kernel(){
    int b = blockIdx.x;
    if (threadIdx.x == 0){
        float w[TOPK]; float mx = -1e30f;
        #pragma unroll
        for (int t = 0; t < TOPK; t++){ w[t] = d_mv[b*256 + d_delays[t]]; mx = fmaxf(mx, w[t]); }
        float s = 0.f;
        #pragma unroll
        for (int t = 0; t < TOPK; t++){ w[t] = expf(w[t]-mx); s += w[t]; }
        #pragma unroll
        for (int t = 0; t < TOPK; t++) d_tc[b*TOPK + t] = w[t]/s;
    }
}

// ---------------- attention softmax: reads raw S fp32, writes packed attn ----------
__global__ void __launch_bounds__(256) softmax_kernel(){
    int row = blockIdx.x;           // (b*2+h)*256 + i
    int b = row >> 9;
    int j = threadIdx.x;
    float v = d_S[(long long)row*256 + j] * 0.125f + d_maskv[b*256 + j];
    __shared__ float red[256];
    __shared__ float val[256];
    red[j] = v; __syncthreads();
    for (int s = 128; s > 0; s >>= 1){ if (j < s) red[j] = fmaxf(red[j], red[j+s]); __syncthreads(); }
    float mx = red[0]; __syncthreads();
    float e = expf(v - mx);
    red[j] = e; __syncthreads();
    for (int s = 128; s > 0; s >>= 1){ if (j < s) red[j] += red[j+s]; __syncthreads(); }
    val[j] = e / red[0];
    __syncthreads();
    if (j < 128){
        uint32_t h, l;
        splitpack(val[2*j], val[2*j+1], h, l);
        d_Sp_hi[(long long)row*128 + j] = h;
        d_Sp_lo[(long long)row*128 + j] = l;
    }
}

// ---------------- freq branch: comb = 0.9 * sum_t v[(l+delay_t)%L] * tc[b,t] --------
__global__ void freq_kernel(){
    int bl = blockIdx.x*2 + (threadIdx.x >> 7);
    int d  = threadIdx.x & 127;
    int b  = bl >> 8, l = bl & 255;
    float s = 0.f;
    #pragma unroll
    for (int t = 0; t < TOPK; t++){
        int ll = (l + d_delays[t]) & 255;
        s += d_qkv[((long long)(b*256 + ll))*384 + 256 + d] * d_tc[b*TOPK + t];
    }
    d_comb[(long long)bl*128 + d] = 0.9f * s;
}

// ---------------- final gather ----------------
__global__ void gather_kernel(const int* __restrict__ lengths, float* __restrict__ out){
    int b = blockIdx.x, d = threadIdx.x;
    int l = lengths[b] - 1;
    out[b*128 + d] = d_x[((long long)b*256 + l)*128 + d];
}

// ---------------- host launch ----------------
extern "C" void kernel_launch(void* const* d_in, const int* in_sizes, int n_in,
                              void* d_out, int out_size)
{
    (void)in_sizes; (void)n_in; (void)out_size;
    const int*   paths   = (const int*)  d_in[0];
    const int*   lengths = (const int*)  d_in[1];
    const float* ego     = (const float*)d_in[4];
    const float* pos     = (const float*)d_in[5];
    const float* Wq      = (const float*)d_in[6];
    const float* Wk      = (const float*)d_in[7];
    const float* Wv      = (const float*)d_in[8];
    const float* Wp      = (const float*)d_in[9];
    const float* F1      = (const float*)d_in[10];
    const float* F2      = (const float*)d_in[11];
    float* out = (float*)d_out;

    float *px, *pqkv, *pfqkv, *pS, *pcomb, *pW;
    uint32_t *pxph, *pxpl, *pqkvph, *pqkvpl, *pfqph, *pfqpl, *pSph, *pSpl;
    uint32_t *pcph, *pcpl, *paph, *papl, *phph, *phpl, *pPph, *pPpl;
    uint32_t *pWch, *pWcl, *pWph, *pWpl, *pF1h, *pF1l, *pF2h, *pF2l;
    cudaGetSymbolAddress((void**)&px,    d_x);
    cudaGetSymbolAddress((void**)&pqkv,  d_qkv);
    cudaGetSymbolAddress((void**)&pfqkv, d_fqkv);
    cudaGetSymbolAddress((void**)&pS,    d_S);
    cudaGetSymbolAddress((void**)&pcomb, d_comb);
    cudaGetSymbolAddress((void**)&pW,    d_Wcat);
    cudaGetSymbolAddress((void**)&pxph,  d_xp_hi);   cudaGetSymbolAddress((void**)&pxpl,  d_xp_lo);
    cudaGetSymbolAddress((void**)&pqkvph,d_qkvp_hi); cudaGetSymbolAddress((void**)&pqkvpl,d_qkvp_lo);
    cudaGetSymbolAddress((void**)&pfqph, d_fqkvp_hi);cudaGetSymbolAddress((void**)&pfqpl, d_fqkvp_lo);
    cudaGetSymbolAddress((void**)&pSph,  d_Sp_hi);   cudaGetSymbolAddress((void**)&pSpl,  d_Sp_lo);
    cudaGetSymbolAddress((void**)&pcph,  d_combp_hi);cudaGetSymbolAddress((void**)&pcpl,  d_combp_lo);
    cudaGetSymbolAddress((void**)&paph,  d_ap_hi);   cudaGetSymbolAddress((void**)&papl,  d_ap_lo);
    cudaGetSymbolAddress((void**)&phph,  d_hp_hi);   cudaGetSymbolAddress((void**)&phpl,  d_hp_lo);
    cudaGetSymbolAddress((void**)&pPph,  d_Pp_hi);   cudaGetSymbolAddress((void**)&pPpl,  d_Pp_lo);
    cudaGetSymbolAddress((void**)&pWch,  d_Wcatp_hi);cudaGetSymbolAddress((void**)&pWcl,  d_Wcatp_lo);
    cudaGetSymbolAddress((void**)&pWph,  d_Wpp_hi);  cudaGetSymbolAddress((void**)&pWpl,  d_Wpp_lo);
    cudaGetSymbolAddress((void**)&pF1h,  d_F1p_hi);  cudaGetSymbolAddress((void**)&pF1l,  d_F1p_lo);
    cudaGetSymbolAddress((void**)&pF2h,  d_F2p_hi);  cudaGetSymbolAddress((void**)&pF2l,  d_F2p_lo);

    compute_P_kernel<<<NLay*256, 256>>>();
    embed_kernel<<<Bsz*Lsz, 128>>>(paths, ego, pos);

    const int ML = Bsz*Lsz;   // 65536
    const int BIG = 1 << 30;

    for (int k = 0; k < NLay; k++){
        const float* wq = Wq + k*Dsz*Dsz;
        const float* wk = Wk + k*Dsz*Dsz;
        const float* wv = Wv + k*Dsz*Dsz;
        const float* wp = Wp + k*Dsz*Dsz;
        const float* f1 = F1 + k*Dsz*2*Dsz;
        const float* f2 = F2 + k*2*Dsz*Dsz;

        // weight packing (tiny)
        packW_kernel<<<192, 256>>>(wq, wk, wv);
        packrows_kernel<<<(64*384+255)/256, 256>>>(pW, pWch, pWcl, 384, 64*384);
        packrows_kernel<<<(64*128+255)/256, 256>>>(wp, pWph, pWpl, 128, 64*128);
        packrows_kernel<<<(64*256+255)/256, 256>>>(f1, pF1h, pF1l, 256, 64*256);
        packrows_kernel<<<(128*128+255)/256, 256>>>(f2, pF2h, pF2l, 128, 128*128);

        // qkv projection: C = x @ Wcat (65536 x 384 x 128), fp32 out
        gemm_tc<0,0,128><<<dim3(3, ML/128, 1), 256>>>(
            pxph, pxpl, pWch, pWcl, pqkv, nullptr, nullptr, nullptr,
            ML,384,128, 64,384,384,0, 0,0,0,0, 0,0,0,0, 1, 1.f, 0);

        // row-pair pack of qkv for band's B
        packrows_kernel<<<(32768*384+255)/256, 256>>>(pqkv, pqkvph, pqkvpl, 384, 32768*384);

        // band filter: fqkv[b] = P_k @ qkv[b]; fp32 only for v third, packed all
        gemm_tc<0,0,128><<<dim3(3, 2, Bsz), 256>>>(
            pPph + k*32768, pPpl + k*32768, pqkvph, pqkvpl,
            pfqkv, pfqph, pfqpl, nullptr,
            256,384,256, 128,384,384,192,
            0,0, 49152,0, 98304,0, 49152,0, 1, 1.f, 256);

        // raw scores: S[b,h] = q~ @ k~^T  (packed TB), fp32 out
        gemm_tc<0,1,128><<<dim3(2, 2, Bsz*Hh), 256>>>(
            pfqph, pfqpl, pfqph + 64, pfqpl + 64,
            pS, nullptr, nullptr, nullptr,
            256,256,64, 192,192,256,0,
            49152,32, 49152,32, 131072,65536, 0,0, 2, 1.f, 0);

        diag_sum_kernel<<<256,256>>>();
        topk_kernel<<<1,256>>>();
        weights_kernel<<<256,32>>>();
        softmax_kernel<<<Bsz*Hh*Lsz, 256>>>();
        freq_kernel<<<Bsz*Lsz/2, 256>>>();

        // spatial: comb = freq + 0.1 * att @ v~; packed out only
        gemm_tc<3,2,64><<<dim3(1, 2, Bsz*Hh), 256>>>(
            pSph, pSpl, pfqkv + 256, nullptr,
            pcomb, pcph, pcpl, nullptr,
            256,64,256, 128,384,128,64,
            65536,32768, 98304,64, 32768,64, 16384,32, 2, 0.1f, BIG);

        // a = comb @ Wp + x (packed out only)
        gemm_tc<1,0,128><<<dim3(1, ML/128, 1), 256>>>(
            pcph, pcpl, pWph, pWpl,
            nullptr, paph, papl, px,
            ML,128,128, 64,128,128,64, 0,0,0,0, 0,0,0,0, 1, 1.f, BIG);

        // FFN1 + GELU (packed out only)
        gemm_tc<2,0,128><<<dim3(2, ML/128, 1), 256>>>(
            paph, papl, pF1h, pF1l,
            nullptr, phph, phpl, nullptr,
            ML,256,128, 64,256,256,128, 0,0,0,0, 0,0,0,0, 1, 1.f, BIG);

        // FFN2: x fp32 + packed
        gemm_tc<0,0,128><<<dim3(1, ML/128, 1), 256>>>(
            phph, phpl, pF2h, pF2l,
            px, pxph, pxpl, nullptr,
            ML,128,256, 128,128,128,64, 0,0,0,0, 0,0,0,0, 1, 1.f, 0);
    }

    gather_kernel<<<Bsz, 128>>>(lengths, out);
}